// round 10
// baseline (speedup 1.0000x reference)
#include <cuda_runtime.h>
#include <cuda_bf16.h>

// Shapes (fixed by the problem):
//   se_pred: [64, 6]  float32   (384 elems)
//   target : [64, 512, 512] labels 0..5, int32 on device (16777216 elems)
//   out    : scalar float32 mean BCE loss
//
// Strategy: class-presence via sampling with provable fallback. Each batch is
// owned by one half-warp; its first round unions 128 random labels
// (P(missing a present class) ~ 6*(5/6)^128 ~ 4e-10), with a full-coverage
// scan as the cold path. One CTA, one barrier, no global sync, no atomics.
// Log terms are computed in the shadow of the target DRAM latency.
#define NBATCH   64
#define NCLASS   6
#define PIX      (512 * 512)     // 262144 labels per batch
#define THREADS  1024            // one half-warp (16 threads) per batch
#define MAX_IT   (PIX / 4 / 16)  // 4096 rounds = full coverage fallback

__global__ void __launch_bounds__(THREADS)
se_one_block_kernel(const int* __restrict__ target,
                    const float* __restrict__ se_pred,
                    float* __restrict__ out) {
    const int tid   = threadIdx.x;
    const int lane  = tid & 31;
    const int batch = tid >> 4;          // 64 half-warps -> 64 batches
    const int sub   = tid & 15;          // lane within half-warp
    const unsigned hm = (lane < 16) ? 0x0000FFFFu : 0xFFFF0000u;

    const int4* __restrict__ base = (const int4*)(target + (size_t)batch * PIX);

    // Issue target loads FIRST (the long-latency dependency).
    int4 v0 = base[sub];
    int4 v1 = base[16 + sub];

    // While those are in flight: load this lane's prediction and compute both
    // clamped log terms (MUFU work fully hidden in the LDG shadow).
    // torch BCELoss clamps log at -100; MUFU log is plenty accurate for
    // p in [1e-4, 1-1e-4] (measured rel_err ~1e-7).
    float lp = 0.0f, l1p = 0.0f;
    if (sub < NCLASS) {
        const float p = se_pred[batch * NCLASS + sub];
        lp  = fmaxf(__logf(p),        -100.0f);
        l1p = fmaxf(__logf(1.0f - p), -100.0f);
    }

    // 128 labels unioned per half-warp.
    int mask = (1 << v0.x) | (1 << v0.y) | (1 << v0.z) | (1 << v0.w)
             | (1 << v1.x) | (1 << v1.y) | (1 << v1.z) | (1 << v1.w);
    mask = __reduce_or_sync(hm, mask);       // uniform within half-warp

    if (mask != 0x3F) {                       // cold path: full-coverage scan
        #pragma unroll 1
        for (int i = 2; i < MAX_IT; ++i) {
            int4 v = base[i * 16 + sub];
            mask |= (1 << v.x) | (1 << v.y) | (1 << v.z) | (1 << v.w);
            mask = __reduce_or_sync(hm, mask);
            if (mask == 0x3F) break;
        }
    }

    // Post-REDUX chain is now just select + fma + shuffles.
    float s = 0.0f;
    if (sub < NCLASS) {
        const float t = (float)((mask >> sub) & 1);
        s = -(t * lp + (1.0f - t) * l1p);
    }
    #pragma unroll
    for (int o = 8; o > 0; o >>= 1)
        s += __shfl_xor_sync(hm, s, o);      // offsets 1,2,4,8 stay in half-warp

    __shared__ float part[NBATCH];
    if (sub == 0) part[batch] = s;
    __syncthreads();

    // Warp 0 sums the 64 batch partials.
    if (tid < 32) {
        float v = part[tid] + part[tid + 32];
        #pragma unroll
        for (int o = 16; o > 0; o >>= 1)
            v += __shfl_xor_sync(0xFFFFFFFFu, v, o);
        if (tid == 0) out[0] = v * (1.0f / (NBATCH * NCLASS));
    }
}

extern "C" void kernel_launch(void* const* d_in, const int* in_sizes, int n_in,
                              void* d_out, int out_size) {
    // Robust to input ordering: identify by element count.
    const float* se_pred;
    const int*   target;
    if (in_sizes[0] == NBATCH * NCLASS) {
        se_pred = (const float*)d_in[0];
        target  = (const int*)d_in[1];
    } else {
        se_pred = (const float*)d_in[1];
        target  = (const int*)d_in[0];
    }
    float* out = (float*)d_out;

    se_one_block_kernel<<<1, THREADS>>>(target, se_pred, out);
}

// round 11
// speedup vs baseline: 1.0591x; 1.0591x over previous
#include <cuda_runtime.h>
#include <cuda_bf16.h>

// Shapes (fixed by the problem):
//   se_pred: [64, 6]  float32   (384 elems)
//   target : [64, 512, 512] labels 0..5, int32 on device (16777216 elems)
//   out    : scalar float32 mean BCE loss
//
// Strategy: class-presence via sampling with provable fallback. Each batch is
// owned by one half-warp; its first round unions 128 random labels
// (P(missing a present class) ~ 6*(5/6)^128 ~ 4e-10), with a full-coverage
// scan as the cold path. One CTA, one barrier, no global sync, no atomics.
// DRAM traffic: ~130 KB typical vs 67 MB for a full scan.
#define NBATCH   64
#define NCLASS   6
#define PIX      (512 * 512)     // 262144 labels per batch
#define THREADS  1024            // one half-warp (16 threads) per batch
#define MAX_IT   (PIX / 4 / 16)  // 4096 rounds = full coverage fallback

__global__ void __launch_bounds__(THREADS)
se_one_block_kernel(const int* __restrict__ target,
                    const float* __restrict__ se_pred,
                    float* __restrict__ out) {
    const int tid   = threadIdx.x;
    const int lane  = tid & 31;
    const int batch = tid >> 4;          // 64 half-warps -> 64 batches
    const int sub   = tid & 15;          // lane within half-warp
    const unsigned hm = (lane < 16) ? 0x0000FFFFu : 0xFFFF0000u;

    // Prefetch this lane's prediction NOW so its LDG overlaps the target
    // DRAM latency (lanes 0..5 of each half-warp own the 6 classes).
    float p = 1.0f;
    if (sub < NCLASS) p = se_pred[batch * NCLASS + sub];

    const int4* __restrict__ base = (const int4*)(target + (size_t)batch * PIX);

    // First round: TWO independent 16B loads per lane -> 128 labels unioned
    // per half-warp. The fallback loop below is statically present but
    // essentially never runs.
    int4 v0 = base[sub];
    int4 v1 = base[16 + sub];
    int mask = (1 << v0.x) | (1 << v0.y) | (1 << v0.z) | (1 << v0.w)
             | (1 << v1.x) | (1 << v1.y) | (1 << v1.z) | (1 << v1.w);
    mask = __reduce_or_sync(hm, mask);       // uniform within half-warp

    if (mask != 0x3F) {                       // cold path: full-coverage scan
        #pragma unroll 1
        for (int i = 2; i < MAX_IT; ++i) {
            int4 v = base[i * 16 + sub];
            mask |= (1 << v.x) | (1 << v.y) | (1 << v.z) | (1 << v.w);
            mask = __reduce_or_sync(hm, mask);
            if (mask == 0x3F) break;
        }
    }

    // Per-lane BCE term (lanes 0..5), then half-warp butterfly reduce.
    float s = 0.0f;
    if (sub < NCLASS) {
        const float t   = (float)((mask >> sub) & 1);
        // torch BCELoss clamps log at -100; MUFU-based fast log is plenty
        // accurate for p in [1e-4, 1-1e-4] (measured rel_err ~1e-7).
        const float lp  = fmaxf(__logf(p),        -100.0f);
        const float l1p = fmaxf(__logf(1.0f - p), -100.0f);
        s = -(t * lp + (1.0f - t) * l1p);
    }
    #pragma unroll
    for (int o = 8; o > 0; o >>= 1)
        s += __shfl_xor_sync(hm, s, o);      // offsets 1,2,4,8 stay in half-warp

    __shared__ float part[NBATCH];
    if (sub == 0) part[batch] = s;
    __syncthreads();

    // Warp 0 sums the 64 batch partials.
    if (tid < 32) {
        float v = part[tid] + part[tid + 32];
        #pragma unroll
        for (int o = 16; o > 0; o >>= 1)
            v += __shfl_xor_sync(0xFFFFFFFFu, v, o);
        if (tid == 0) out[0] = v * (1.0f / (NBATCH * NCLASS));
    }
}

extern "C" void kernel_launch(void* const* d_in, const int* in_sizes, int n_in,
                              void* d_out, int out_size) {
    // Robust to input ordering: identify by element count.
    const float* se_pred;
    const int*   target;
    if (in_sizes[0] == NBATCH * NCLASS) {
        se_pred = (const float*)d_in[0];
        target  = (const int*)d_in[1];
    } else {
        se_pred = (const float*)d_in[1];
        target  = (const int*)d_in[0];
    }
    float* out = (float*)d_out;

    se_one_block_kernel<<<1, THREADS>>>(target, se_pred, out);
}